// round 13
// baseline (speedup 1.0000x reference)
#include <cuda_runtime.h>
#include <cuda_fp16.h>
#include <cstdint>
#include <cstring>

// FFReLU loglik via mma.sync m16n8k16 (fp16 in, f32 accum), scalar relu+w2 fold
// with packed fma.rn.f32x2. 8-warp blocks, 2 m16-tiles per warp -> 24 warps/SM.
// out[r,n] = -0.5*(y[n]-mu)^2 - 0.5*log(2pi),  mu = sum_h w2*relu(D[n][h])

#define IN_DIM 13
#define H_DIM 512
#define R_DIM 256
#define N_DIM 2048
#define W_DIM 7168
#define W1_SZ 6656
#define TN 256
#define PITCH 48               // 16 fp16 = 32B data + 16B pad -> conflict-free
#define XH_OFF 0
#define WH_OFF (XH_OFF + TN * PITCH)            // 12288
#define W2F_OFF (WH_OFF + H_DIM * PITCH)        // 36864 f32 (2KB)
#define SMEM_TOTAL (W2F_OFF + H_DIM * 4)        // 38912
#define NEG_HALF_LOG_2PI (-0.918938533204672741780329736406f)

typedef unsigned long long ull;

__device__ __forceinline__ uint32_t smem_u32(const void* p) {
    uint32_t a;
    asm("{ .reg .u64 t; cvta.to.shared.u64 t, %1; cvt.u32.u64 %0, t; }" : "=r"(a) : "l"(p));
    return a;
}

__device__ __forceinline__ void ldm4(uint32_t r[4], uint32_t addr) {
    asm volatile("ldmatrix.sync.aligned.m8n8.x4.shared.b16 {%0,%1,%2,%3}, [%4];"
                 : "=r"(r[0]), "=r"(r[1]), "=r"(r[2]), "=r"(r[3]) : "r"(addr));
}

__device__ __forceinline__ void mma_fp16(float d[4], const uint32_t a[4],
                                         uint32_t b0, uint32_t b1) {
    asm volatile(
        "mma.sync.aligned.m16n8k16.row.col.f32.f16.f16.f32 "
        "{%0,%1,%2,%3}, {%4,%5,%6,%7}, {%8,%9}, {%0,%1,%2,%3};"
        : "+f"(d[0]), "+f"(d[1]), "+f"(d[2]), "+f"(d[3])
        : "r"(a[0]), "r"(a[1]), "r"(a[2]), "r"(a[3]), "r"(b0), "r"(b1));
}

__device__ __forceinline__ void ffma2(ull& d, ull a, ull b) {
    asm("fma.rn.f32x2 %0, %1, %2, %0;" : "+l"(d) : "l"(a), "l"(b));
}
__device__ __forceinline__ ull pack2(float lo, float hi) {
    ull r;
    asm("mov.b64 %0, {%1, %2};" : "=l"(r) : "f"(lo), "f"(hi));
    return r;
}
__device__ __forceinline__ void unpack2(ull v, float& lo, float& hi) {
    asm("mov.b64 {%0, %1}, %2;" : "=f"(lo), "=f"(hi) : "l"(v));
}

// row of 13 floats -> fp16 tile row (k padded to 16 with zeros)
__device__ __forceinline__ void pack_row(char* smem, int off, int row, const float* v) {
    uint32_t hi[8];
#pragma unroll
    for (int p = 0; p < 8; p++) {
        float a0 = (2 * p < IN_DIM) ? v[2 * p] : 0.f;
        float a1 = (2 * p + 1 < IN_DIM) ? v[2 * p + 1] : 0.f;
        __half2 hp;
        hp.x = __float2half_rn(a0); hp.y = __float2half_rn(a1);
        memcpy(&hi[p], &hp, 4);
    }
    char* hr = smem + off + row * PITCH;
    ((uint4*)hr)[0] = make_uint4(hi[0], hi[1], hi[2], hi[3]);
    ((uint4*)hr)[1] = make_uint4(hi[4], hi[5], hi[6], hi[7]);
}

__global__ __launch_bounds__(256, 3)
void ffrelu_hmma_kernel(const float* __restrict__ x,
                        const float* __restrict__ y,
                        const float* __restrict__ w,
                        float* __restrict__ out) {
    extern __shared__ char smem[];
    const uint32_t sb = smem_u32(smem);
    const int tid = threadIdx.x;
    const int lane = tid & 31;
    const int wid = tid >> 5;            // warp 0..7 owns n-rows 32*wid..+31
    const int g8 = lane & 7;
    const int grp = lane >> 3;
    const int c4 = lane & 3;
    const int g = lane >> 2;
    const int nblk = blockIdx.x * TN;
    const int r = blockIdx.y;
    const float* wr = w + (size_t)r * W_DIM;

    // ---- stage x tile: 1 row/thread ----
    {
        const float* xr = x + (size_t)(nblk + tid) * IN_DIM;
        float v[IN_DIM];
#pragma unroll
        for (int k = 0; k < IN_DIM; k++) v[k] = xr[k];
        pack_row(smem, XH_OFF, tid, v);
    }
    // ---- stage w1: 2 rows/thread ----
#pragma unroll
    for (int i = 0; i < 2; i++) {
        const int h = tid + i * 256;
        const float* wrow = wr + h * IN_DIM;
        float v[IN_DIM];
#pragma unroll
        for (int k = 0; k < IN_DIM; k++) v[k] = wrow[k];
        pack_row(smem, WH_OFF, h, v);
    }
    // ---- stage w2 (f32) ----
#pragma unroll
    for (int i = 0; i < 2; i++)
        ((float*)(smem + W2F_OFF))[tid + 256 * i] = wr[W1_SZ + tid + 256 * i];
    __syncthreads();

    // ---- A fragments once per warp: 2 m16-tiles ----
    uint32_t a_hi[2][4];
#pragma unroll
    for (int mt = 0; mt < 2; mt++) {
        uint32_t aaddr = sb + XH_OFF +
            (32 * wid + 16 * mt + (grp & 1) * 8 + g8) * PITCH + (grp >> 1) * 16;
        ldm4(a_hi[mt], aaddr);
    }

    // B: per 16-h chunk, x4 ldmatrix
    uint32_t bAddr = sb + WH_OFF + ((grp >> 1) * 8 + g8) * PITCH + (grp & 1) * 16;

    ull mu2[2][2];
#pragma unroll
    for (int mt = 0; mt < 2; mt++) { mu2[mt][0] = 0ull; mu2[mt][1] = 0ull; }

    // software-pipelined B loads
    uint32_t bcur[4];
    ldm4(bcur, bAddr);
    bAddr += 16 * PITCH;

#pragma unroll 1
    for (int dc = 0; dc < H_DIM / 16; dc++) {
        uint32_t bnxt[4];
        if (dc < H_DIM / 16 - 1) {
            ldm4(bnxt, bAddr);
            bAddr += 16 * PITCH;
        }
#pragma unroll
        for (int half = 0; half < 2; half++) {
            const float2 w2p = *(const float2*)(smem + W2F_OFF +
                                (dc * 16 + half * 8 + 2 * c4) * 4);
            const ull w2pair = pack2(w2p.x, w2p.y);
            const uint32_t b0 = bcur[2 * half], b1 = bcur[2 * half + 1];
#pragma unroll
            for (int mt = 0; mt < 2; mt++) {
                float d[4] = {0.f, 0.f, 0.f, 0.f};
                mma_fp16(d, a_hi[mt], b0, b1);
                ffma2(mu2[mt][0], w2pair, pack2(fmaxf(d[0], 0.f), fmaxf(d[1], 0.f)));
                ffma2(mu2[mt][1], w2pair, pack2(fmaxf(d[2], 0.f), fmaxf(d[3], 0.f)));
            }
        }
#pragma unroll
        for (int i = 0; i < 4; i++) bcur[i] = bnxt[i];
    }

    // ---- horizontal add + butterfly over 4 col-threads ----
    float mu[2][2];
#pragma unroll
    for (int mt = 0; mt < 2; mt++)
#pragma unroll
        for (int i = 0; i < 2; i++) {
            float lo, hi;
            unpack2(mu2[mt][i], lo, hi);
            float v = lo + hi;
            v += __shfl_xor_sync(0xffffffffu, v, 1);
            v += __shfl_xor_sync(0xffffffffu, v, 2);
            mu[mt][i] = v;
        }

    // lane c4 stores m16-tile (c4&1), rows g and g+8; tiles indexed by c4 parity
    const int mtSel = c4 & 1;
    const int n = nblk + 32 * wid + 16 * mtSel + g;
    if (c4 < 2) {
        const float r0 = y[n] - mu[mtSel][0];
        out[(size_t)r * N_DIM + n] = fmaf(-0.5f * r0, r0, NEG_HALF_LOG_2PI);
        const float r1 = y[n + 8] - mu[mtSel][1];
        out[(size_t)r * N_DIM + n + 8] = fmaf(-0.5f * r1, r1, NEG_HALF_LOG_2PI);
    }
}

extern "C" void kernel_launch(void* const* d_in, const int* in_sizes, int n_in,
                              void* d_out, int out_size) {
    const float* x = (const float*)d_in[0];   // [2048,13]
    const float* y = (const float*)d_in[1];   // [2048,1]
    const float* w = (const float*)d_in[2];   // [256,7168]
    float* out = (float*)d_out;               // [256,2048]

    cudaFuncSetAttribute(ffrelu_hmma_kernel,
                         cudaFuncAttributeMaxDynamicSharedMemorySize, SMEM_TOTAL);
    dim3 grid(N_DIM / TN, R_DIM);   // 8 x 256
    ffrelu_hmma_kernel<<<grid, 256, SMEM_TOTAL>>>(x, y, w, out);
}

// round 14
// speedup vs baseline: 1.1848x; 1.1848x over previous
#include <cuda_runtime.h>
#include <cuda_fp16.h>
#include <cstdint>
#include <cstring>

// FFReLU loglik, tensorized fold + fused relu-cvt:
//   main GEMM D = x @ w1^T (fp16 in, f32 accum, m16n8k16)
//   relu via cvt.rn.relu.f16x2.f32 (fused), fold via second MMA vs B=[w2|0..]
// 256-thread blocks, TN=512 (4 m16-tiles per warp) for B-load amortization.
// out[r,n] = -0.5*(y[n]-mu)^2 - 0.5*log(2pi)

#define IN_DIM 13
#define H_DIM 512
#define R_DIM 256
#define N_DIM 2048
#define W_DIM 7168
#define W1_SZ 6656
#define TN 512
#define PITCH 48               // 16 fp16 = 32B data + 16B pad -> conflict-free
#define XH_OFF 0
#define WH_OFF (XH_OFF + TN * PITCH)            // 24576
#define W2H_OFF (WH_OFF + H_DIM * PITCH)        // 49152 fp16 pairs (1KB)
#define SMEM_TOTAL (W2H_OFF + H_DIM * 2)        // 50176
#define NEG_HALF_LOG_2PI (-0.918938533204672741780329736406f)

__device__ __forceinline__ uint32_t smem_u32(const void* p) {
    uint32_t a;
    asm("{ .reg .u64 t; cvta.to.shared.u64 t, %1; cvt.u32.u64 %0, t; }" : "=r"(a) : "l"(p));
    return a;
}

__device__ __forceinline__ void ldm4(uint32_t r[4], uint32_t addr) {
    asm volatile("ldmatrix.sync.aligned.m8n8.x4.shared.b16 {%0,%1,%2,%3}, [%4];"
                 : "=r"(r[0]), "=r"(r[1]), "=r"(r[2]), "=r"(r[3]) : "r"(addr));
}

__device__ __forceinline__ void mma_fp16(float d[4], const uint32_t a[4],
                                         uint32_t b0, uint32_t b1) {
    asm volatile(
        "mma.sync.aligned.m16n8k16.row.col.f32.f16.f16.f32 "
        "{%0,%1,%2,%3}, {%4,%5,%6,%7}, {%8,%9}, {%0,%1,%2,%3};"
        : "+f"(d[0]), "+f"(d[1]), "+f"(d[2]), "+f"(d[3])
        : "r"(a[0]), "r"(a[1]), "r"(a[2]), "r"(a[3]), "r"(b0), "r"(b1));
}

// fused relu + pack two f32 -> f16x2 {lo, hi}
__device__ __forceinline__ uint32_t cvt_relu_h2(float lo, float hi) {
    uint32_t p;
    asm("cvt.rn.relu.f16x2.f32 %0, %1, %2;" : "=r"(p) : "f"(hi), "f"(lo));
    return p;
}
__device__ __forceinline__ uint32_t cvt_h2(float lo, float hi) {
    uint32_t p;
    asm("cvt.rn.f16x2.f32 %0, %1, %2;" : "=r"(p) : "f"(hi), "f"(lo));
    return p;
}

// row of 13 floats -> fp16 tile row (k padded to 16 with zeros)
__device__ __forceinline__ void pack_row(char* smem, int off, int row, const float* v) {
    uint32_t hi[8];
#pragma unroll
    for (int p = 0; p < 8; p++) {
        float a0 = (2 * p < IN_DIM) ? v[2 * p] : 0.f;
        float a1 = (2 * p + 1 < IN_DIM) ? v[2 * p + 1] : 0.f;
        __half2 hp;
        hp.x = __float2half_rn(a0); hp.y = __float2half_rn(a1);
        memcpy(&hi[p], &hp, 4);
    }
    char* hr = smem + off + row * PITCH;
    ((uint4*)hr)[0] = make_uint4(hi[0], hi[1], hi[2], hi[3]);
    ((uint4*)hr)[1] = make_uint4(hi[4], hi[5], hi[6], hi[7]);
}

__global__ __launch_bounds__(256, 3)
void ffrelu_hmma_kernel(const float* __restrict__ x,
                        const float* __restrict__ y,
                        const float* __restrict__ w,
                        float* __restrict__ out) {
    extern __shared__ char smem[];
    const uint32_t sb = smem_u32(smem);
    const int tid = threadIdx.x;
    const int lane = tid & 31;
    const int wid = tid >> 5;            // warp 0..7 owns n-rows 64*wid..+63
    const int g8 = lane & 7;
    const int grp = lane >> 3;
    const int c4 = lane & 3;
    const int g = lane >> 2;
    const int nblk = blockIdx.x * TN;
    const int r = blockIdx.y;
    const float* wr = w + (size_t)r * W_DIM;

    // ---- stage x tile: 2 rows/thread ----
#pragma unroll
    for (int i = 0; i < 2; i++) {
        const int row = tid + i * 256;
        const float* xr = x + (size_t)(nblk + row) * IN_DIM;
        float v[IN_DIM];
#pragma unroll
        for (int k = 0; k < IN_DIM; k++) v[k] = xr[k];
        pack_row(smem, XH_OFF, row, v);
    }
    // ---- stage w1: 2 rows/thread ----
#pragma unroll
    for (int i = 0; i < 2; i++) {
        const int h = tid + i * 256;
        const float* wrow = wr + h * IN_DIM;
        float v[IN_DIM];
#pragma unroll
        for (int k = 0; k < IN_DIM; k++) v[k] = wrow[k];
        pack_row(smem, WH_OFF, h, v);
    }
    // ---- stage w2 as fp16 pairs (256 uint32, 1/thread) ----
    ((uint32_t*)(smem + W2H_OFF))[tid] =
        cvt_h2(wr[W1_SZ + 2 * tid], wr[W1_SZ + 2 * tid + 1]);
    __syncthreads();

    // ---- A fragments once per warp: 4 m16-tiles ----
    uint32_t a_hi[4][4];
#pragma unroll
    for (int mt = 0; mt < 4; mt++) {
        uint32_t aaddr = sb + XH_OFF +
            (64 * wid + 16 * mt + (grp & 1) * 8 + g8) * PITCH + (grp >> 1) * 16;
        ldm4(a_hi[mt], aaddr);
    }

    // B (w1): per 16-h chunk, x4 ldmatrix
    uint32_t bAddr = sb + WH_OFF + ((grp >> 1) * 8 + g8) * PITCH + (grp & 1) * 16;
    const uint32_t* w2h = (const uint32_t*)(smem + W2H_OFF);

    // persistent f32 mu accumulators (reduction-MMA C), col 0 live
    float acc[4][4];
#pragma unroll
    for (int mt = 0; mt < 4; mt++)
#pragma unroll
        for (int i = 0; i < 4; i++) acc[mt][i] = 0.f;

    // software-pipelined B loads
    uint32_t bcur[4];
    ldm4(bcur, bAddr);
    bAddr += 16 * PITCH;

#pragma unroll 1
    for (int dc = 0; dc < H_DIM / 16; dc++) {
        uint32_t bnxt[4];
        if (dc < H_DIM / 16 - 1) {
            ldm4(bnxt, bAddr);
            bAddr += 16 * PITCH;
        }
        // reduction-B: col 0 = w2[dc*16..+15], cols 1-7 zero (lanes 0-3 carry)
        const uint32_t wb0 = (lane < 4) ? w2h[dc * 8 + c4] : 0u;
        const uint32_t wb1 = (lane < 4) ? w2h[dc * 8 + 4 + c4] : 0u;

#pragma unroll
        for (int mt = 0; mt < 4; mt++) {
            float d0[4] = {0.f, 0.f, 0.f, 0.f};
            float d1[4] = {0.f, 0.f, 0.f, 0.f};
            mma_fp16(d0, a_hi[mt], bcur[0], bcur[1]);   // h-cols 0-7
            mma_fp16(d1, a_hi[mt], bcur[2], bcur[3]);   // h-cols 8-15
            uint32_t ra[4];
            ra[0] = cvt_relu_h2(d0[0], d0[1]);   // row g,   k0-7 pair
            ra[1] = cvt_relu_h2(d0[2], d0[3]);   // row g+8, k0-7
            ra[2] = cvt_relu_h2(d1[0], d1[1]);   // row g,   k8-15
            ra[3] = cvt_relu_h2(d1[2], d1[3]);   // row g+8, k8-15
            mma_fp16(acc[mt], ra, wb0, wb1);     // mu += relu(D) @ w2
        }
#pragma unroll
        for (int i = 0; i < 4; i++) bcur[i] = bnxt[i];
    }

    // ---- epilogue: col 0 of reduction output = mu (c4==0 lanes) ----
    if (c4 == 0) {
#pragma unroll
        for (int mt = 0; mt < 4; mt++) {
            const int n = nblk + 64 * wid + 16 * mt + g;
            const float r0 = y[n] - acc[mt][0];            // row g
            out[(size_t)r * N_DIM + n] = fmaf(-0.5f * r0, r0, NEG_HALF_LOG_2PI);
            const float r1 = y[n + 8] - acc[mt][2];        // row g+8
            out[(size_t)r * N_DIM + n + 8] = fmaf(-0.5f * r1, r1, NEG_HALF_LOG_2PI);
        }
    }
}

extern "C" void kernel_launch(void* const* d_in, const int* in_sizes, int n_in,
                              void* d_out, int out_size) {
    const float* x = (const float*)d_in[0];   // [2048,13]
    const float* y = (const float*)d_in[1];   // [2048,1]
    const float* w = (const float*)d_in[2];   // [256,7168]
    float* out = (float*)d_out;               // [256,2048]

    cudaFuncSetAttribute(ffrelu_hmma_kernel,
                         cudaFuncAttributeMaxDynamicSharedMemorySize, SMEM_TOTAL);
    dim3 grid(N_DIM / TN, R_DIM);   // 4 x 256
    ffrelu_hmma_kernel<<<grid, 256, SMEM_TOTAL>>>(x, y, w, out);
}